// round 1
// baseline (speedup 1.0000x reference)
#include <cuda_runtime.h>
#include <math.h>

#define NE 100000
#define NR 400
#define NT 1000000
#define B  32
#define DH 512
#define T_STEPS 3

// ---------------- device scratch (no allocations allowed) ----------------
__device__ float g_e[T_STEPS + 1][NE * B];   // entity dists, (NE,B) layout. g_e[0] = e_s^T
__device__ float g_ansT[NE * B];             // answers^T, (NE,B)
__device__ float g_relT[NR * B];             // current step rel_dist^T, (NR,B)
__device__ float g_cq[B * DH];
__device__ int   g_argmax[T_STEPS * B];
__device__ float g_gt[B];
__device__ float g_cond[B];
__device__ float g_m3[B];
__device__ float g_sums[B];
__device__ float g_h[B * DH];                // normed @ ent_emb  (B,DH)

// ---------------- transpose (B,NE) -> (NE,B) for e_s and answers ----------------
__global__ void k_transpose_in(const float* __restrict__ es,
                               const float* __restrict__ ans) {
    __shared__ float tile[32][33];
    int i0 = blockIdx.x * 32;
    const float* src = (blockIdx.y == 0) ? es : ans;
    float* dst = (blockIdx.y == 0) ? g_e[0] : g_ansT;
    int tx = threadIdx.x, ty = threadIdx.y;
    tile[ty][tx] = src[(size_t)ty * NE + i0 + tx];   // src[b=ty][i0+tx]
    __syncthreads();
    dst[(size_t)(i0 + ty) * B + tx] = tile[tx][ty];  // dst[i0+ty][b=tx]
}

// ---------------- cq_t = tanh(q_emb @ W[t]^T + b[t]) ----------------
__global__ void k_cq(const int* __restrict__ questions,
                     const float* __restrict__ rel_emb,
                     const float* __restrict__ step_W,
                     const float* __restrict__ step_b, int t) {
    __shared__ float q[DH];
    int b = blockIdx.x, j = threadIdx.x;
    int qi = questions[b];
    q[j] = rel_emb[(size_t)qi * DH + j];
    __syncthreads();
    const float4* W = (const float4*)(step_W + (size_t)t * DH * DH + (size_t)j * DH);
    const float4* qv = (const float4*)q;
    float acc = step_b[t * DH + j];
#pragma unroll 8
    for (int k = 0; k < DH / 4; k++) {
        float4 w = W[k]; float4 x = qv[k];
        acc += w.x * x.x + w.y * x.y + w.z * x.z + w.w * x.w;
    }
    g_cq[b * DH + j] = tanhf(acc);
}

// ---------------- rel_dist = softmax(cq @ rel_emb^T), + argmax, + gt ----------------
__global__ void k_rel(const float* __restrict__ rel_emb,
                      const int* __restrict__ questions, int t) {
    __shared__ float scq[DH];
    __shared__ float red[512];
    __shared__ int   redi[512];
    int b = blockIdx.x, r = threadIdx.x;
    scq[r] = g_cq[b * DH + r];
    __syncthreads();
    float logit = -1e30f;
    if (r < NR) {
        const float4* E = (const float4*)(rel_emb + (size_t)r * DH);
        const float4* q = (const float4*)scq;
        float acc = 0.f;
#pragma unroll 8
        for (int k = 0; k < DH / 4; k++) {
            float4 w = E[k]; float4 x = q[k];
            acc += w.x * x.x + w.y * x.y + w.z * x.z + w.w * x.w;
        }
        logit = acc;
    }
    // max + first-index argmax
    red[r] = logit; redi[r] = (r < NR) ? r : 0x7fffffff;
    __syncthreads();
    for (int s = 256; s > 0; s >>= 1) {
        if (r < s) {
            float a = red[r], c = red[r + s];
            int ia = redi[r], ic = redi[r + s];
            if (c > a || (c == a && ic < ia)) { red[r] = c; redi[r] = ic; }
        }
        __syncthreads();
    }
    float mx = red[0];
    int amax = redi[0];
    __syncthreads();
    float e = (r < NR) ? expf(logit - mx) : 0.f;
    red[r] = e;
    __syncthreads();
    for (int s = 256; s > 0; s >>= 1) {
        if (r < s) red[r] += red[r + s];
        __syncthreads();
    }
    float sum = red[0];
    if (r < NR) {
        float p = e / sum;
        g_relT[r * B + b] = p;
        if (t == 0 && r == questions[b]) g_gt[b] = p;
    }
    if (r == 0) g_argmax[t * B + b] = amax;
}

// ---------------- per-batch mask flags ----------------
__global__ void k_flags(int t) {
    int b = threadIdx.x;
    int prev = g_argmax[(t - 1) * B + b], curr = g_argmax[t * B + b];
    int d = prev - curr; if (d < 0) d = -d;
    int mn = prev < curr ? prev : curr;
    g_cond[b] = (d == 1 && (mn & 1) == 0) ? 1.f : 0.f;
    if (t == T_STEPS - 1) {
        int ns = 0;
        for (int k = 0; k < T_STEPS; k++) ns += (g_argmax[k * B + b] == 0);
        g_m3[b] = (ns == 1) ? 1.f : 0.f;
    }
}

// ---------------- zero helpers ----------------
__global__ void k_zero_buf(int which) {
    int i = blockIdx.x * blockDim.x + threadIdx.x;
    if (i < NE * B) g_e[which][i] = 0.f;
}
__global__ void k_zero_hs() {
    int i = blockIdx.x * blockDim.x + threadIdx.x;
    if (i < B * DH) g_h[i] = 0.f;
    if (i < B) g_sums[i] = 0.f;
}

// ---------------- follow: scatter-add over triples (warp per triple, lane=batch) ----------------
__global__ void __launch_bounds__(256) k_follow(const int* __restrict__ subj,
                                                const int* __restrict__ rel,
                                                const int* __restrict__ obj, int t) {
    int w = blockIdx.x * 8 + (threadIdx.x >> 5);
    int lane = threadIdx.x & 31;
    int s = __ldg(subj + w), r = __ldg(rel + w), o = __ldg(obj + w);
    float x = __ldg(&g_e[t][(size_t)s * B + lane]) * g_relT[r * B + lane];
    if (x != 0.f) atomicAdd(&g_e[t + 1][(size_t)o * B + lane], x);
}

// ---------------- post-follow pointwise (subtract/clamp/masks), in place on g_e[t+1] ----------------
__global__ void k_post(int t) {
    int idx = blockIdx.x * blockDim.x + threadIdx.x;
    if (idx >= NE * B) return;
    int b = idx & 31;
    float v = g_e[t + 1][idx];
    if (t == 0) v -= g_ansT[idx] * g_gt[b];
    if (v > 1.f) v = 1.f;                           // v/z with z=v where v>1
    if (t >= 1) {
        if (g_cond[b] != 0.f && g_e[t - 1][idx] > 0.9f) v = 0.f;
    }
    if (t == T_STEPS - 1) v *= (1.f - g_m3[b] * g_e[0][idx]);
    g_e[t + 1][idx] = v;
}

// ---------------- per-batch sums of e_score ----------------
__global__ void k_sums() {
    __shared__ float part[8][32];
    int tid = threadIdx.x, lane = tid & 31, wp = tid >> 5;
    float acc = 0.f;
    for (int idx = blockIdx.x * 256 + tid; idx < NE * B; idx += gridDim.x * 256)
        acc += g_e[T_STEPS][idx];                   // b == lane by construction
    part[wp][lane] = acc;
    __syncthreads();
    if (wp == 0) {
        float s = 0.f;
        for (int k = 0; k < 8; k++) s += part[k][lane];
        atomicAdd(&g_sums[lane], s);
    }
}

// ---------------- e_score output: transpose (NE,B) -> (B,NE) ----------------
__global__ void k_outT(float* __restrict__ out) {
    __shared__ float tile[32][33];
    int i0 = blockIdx.x * 32;
    int tx = threadIdx.x, ty = threadIdx.y;
    tile[ty][tx] = g_e[T_STEPS][(size_t)(i0 + ty) * B + tx];
    __syncthreads();
    out[(size_t)ty * NE + i0 + tx] = tile[tx][ty];
}

// ---------------- h = (e_score / (sum+1e-6)) @ ent_emb  (chunked, atomics) ----------------
#define HCHUNK 256
__global__ void __launch_bounds__(512) k_h(const float* __restrict__ ent_emb) {
    int b = threadIdx.x & 31;
    int dg = threadIdx.x >> 5;                      // 0..15, owns dims dg*32..dg*32+31
    int i0 = blockIdx.x * HCHUNK;
    float inv = 1.f / (g_sums[b] + 1e-6f);
    float acc[32];
#pragma unroll
    for (int k = 0; k < 32; k++) acc[k] = 0.f;
    int iend = i0 + HCHUNK; if (iend > NE) iend = NE;
    for (int i = i0; i < iend; i++) {
        float ev = g_e[T_STEPS][(size_t)i * B + b] * inv;
        const float4* wp = (const float4*)(ent_emb + (size_t)i * DH + dg * 32);
#pragma unroll
        for (int k = 0; k < 8; k++) {
            float4 w = wp[k];
            acc[4 * k + 0] += ev * w.x; acc[4 * k + 1] += ev * w.y;
            acc[4 * k + 2] += ev * w.z; acc[4 * k + 3] += ev * w.w;
        }
    }
#pragma unroll
    for (int k = 0; k < 32; k++)
        atomicAdd(&g_h[b * DH + dg * 32 + k], acc[k]);
}

// ---------------- pred = h @ ent_emb^T + bias  (smem-tiled GEMM, 32x64 tiles) ----------------
__global__ void __launch_bounds__(256) k_pred(const float* __restrict__ ent_emb,
                                              const float* __restrict__ ent_bias,
                                              float* __restrict__ out) {
    __shared__ float sh[32][33];   // h k-tile [b][kk]
    __shared__ float se[64][33];   // ent_emb k-tile [n][kk]
    int i0 = blockIdx.x * 64;
    int tid = threadIdx.x;
    int n = tid & 63;
    int m0 = (tid >> 6) * 8;       // 8 batches per thread
    float acc[8];
#pragma unroll
    for (int j = 0; j < 8; j++) acc[j] = 0.f;
    for (int kt = 0; kt < DH; kt += 32) {
        for (int l = tid; l < 32 * 32; l += 256) {
            int bb = l >> 5, kk = l & 31;
            sh[bb][kk] = g_h[bb * DH + kt + kk];
        }
        for (int l = tid; l < 64 * 32; l += 256) {
            int nn = l >> 5, kk = l & 31;
            int ii = i0 + nn;
            se[nn][kk] = (ii < NE) ? ent_emb[(size_t)ii * DH + kt + kk] : 0.f;
        }
        __syncthreads();
#pragma unroll
        for (int kk = 0; kk < 32; kk++) {
            float w = se[n][kk];
#pragma unroll
            for (int j = 0; j < 8; j++) acc[j] += sh[m0 + j][kk] * w;
        }
        __syncthreads();
    }
    int i = i0 + n;
    if (i < NE) {
        float bias = ent_bias[i];
#pragma unroll
        for (int j = 0; j < 8; j++) out[(size_t)(m0 + j) * NE + i] = acc[j] + bias;
    }
}

// ---------------- driver ----------------
extern "C" void kernel_launch(void* const* d_in, const int* in_sizes, int n_in,
                              void* d_out, int out_size) {
    const int*   questions = (const int*)d_in[0];
    const float* e_s       = (const float*)d_in[1];
    const float* answers   = (const float*)d_in[2];
    const int*   subj      = (const int*)d_in[3];
    const int*   rel       = (const int*)d_in[4];
    const int*   obj       = (const int*)d_in[5];
    const float* rel_emb   = (const float*)d_in[6];
    const float* step_W    = (const float*)d_in[7];
    const float* step_b    = (const float*)d_in[8];
    const float* ent_emb   = (const float*)d_in[9];
    const float* ent_bias  = (const float*)d_in[10];
    float* out = (float*)d_out;

    k_transpose_in<<<dim3(NE / 32, 2), dim3(32, 32)>>>(e_s, answers);

    for (int t = 0; t < T_STEPS; t++) {
        k_cq<<<B, DH>>>(questions, rel_emb, step_W, step_b, t);
        k_rel<<<B, 512>>>(rel_emb, questions, t);
        if (t > 0) k_flags<<<1, B>>>(t);
        k_zero_buf<<<(NE * B + 255) / 256, 256>>>(t + 1);
        k_follow<<<NT / 8, 256>>>(subj, rel, obj, t);
        k_post<<<(NE * B + 255) / 256, 256>>>(t);
    }

    k_zero_hs<<<(B * DH + 511) / 512, 512>>>();
    k_sums<<<512, 256>>>();
    k_outT<<<NE / 32, dim3(32, 32)>>>(out);
    k_h<<<(NE + HCHUNK - 1) / HCHUNK, 512>>>(ent_emb);
    k_pred<<<(NE + 63) / 64, 256>>>(ent_emb, ent_bias, out + (size_t)B * NE);
}

// round 2
// speedup vs baseline: 1.7510x; 1.7510x over previous
#include <cuda_runtime.h>
#include <math.h>

#define NE 100000
#define NR 400
#define NT 1000000
#define B  32
#define DH 512
#define T_STEPS 3
#define HB 148   // k_h partial blocks

// ---------------- device scratch (no allocations allowed) ----------------
__device__ float g_e[T_STEPS + 1][NE * B];   // entity dists, (NE,B) layout. g_e[0] = e_s^T
__device__ float g_ansT[NE * B];             // answers^T, (NE,B)
__device__ float g_relT[NR * B];             // current step rel_dist^T, (NR,B)
__device__ float g_cq[B * DH];
__device__ int   g_argmax[T_STEPS * B];
__device__ float g_gt[B];
__device__ float g_cond[B];
__device__ float g_m3[B];
__device__ float g_sums[B];
__device__ float g_h[B * DH];                // normed @ ent_emb  (B,DH) row-major per batch
__device__ unsigned char g_mask[NE];         // "any batch lane nonzero" for current e state
__device__ int   g_nact;                     // active entity count at final step
__device__ int   g_act[NE];                  // active entity list
__device__ float g_hpart[HB][DH * B];        // per-block partials for k_h, [blk][d*B+b]

// ---------------- transpose (B,NE) -> (NE,B) for e_s and answers, + initial mask ----------------
__global__ void k_transpose_in(const float* __restrict__ es,
                               const float* __restrict__ ans) {
    __shared__ float tile[32][33];
    int i0 = blockIdx.x * 32;
    const float* src = (blockIdx.y == 0) ? es : ans;
    float* dst = (blockIdx.y == 0) ? g_e[0] : g_ansT;
    int tx = threadIdx.x, ty = threadIdx.y;
    tile[ty][tx] = src[(size_t)ty * NE + i0 + tx];   // src[b=ty][i0+tx]
    __syncthreads();
    float v = tile[tx][ty];                          // entity i0+ty, batch tx
    dst[(size_t)(i0 + ty) * B + tx] = v;
    if (blockIdx.y == 0) {
        unsigned m = __ballot_sync(0xffffffffu, v != 0.f);  // warp == fixed ty
        if (tx == 0) g_mask[i0 + ty] = (m != 0u) ? 1 : 0;
    }
}

// ---------------- cq_t = tanh(q_emb @ W[t]^T + b[t]) ----------------
__global__ void k_cq(const int* __restrict__ questions,
                     const float* __restrict__ rel_emb,
                     const float* __restrict__ step_W,
                     const float* __restrict__ step_b, int t) {
    __shared__ float q[DH];
    int b = blockIdx.x, j = threadIdx.x;
    int qi = questions[b];
    q[j] = rel_emb[(size_t)qi * DH + j];
    __syncthreads();
    const float4* W = (const float4*)(step_W + (size_t)t * DH * DH + (size_t)j * DH);
    const float4* qv = (const float4*)q;
    float acc = step_b[t * DH + j];
#pragma unroll 8
    for (int k = 0; k < DH / 4; k++) {
        float4 w = W[k]; float4 x = qv[k];
        acc += w.x * x.x + w.y * x.y + w.z * x.z + w.w * x.w;
    }
    g_cq[b * DH + j] = tanhf(acc);
}

// ---------------- rel_dist = softmax(cq @ rel_emb^T), + argmax, + gt ----------------
__global__ void k_rel(const float* __restrict__ rel_emb,
                      const int* __restrict__ questions, int t) {
    __shared__ float scq[DH];
    __shared__ float red[512];
    __shared__ int   redi[512];
    int b = blockIdx.x, r = threadIdx.x;
    scq[r] = g_cq[b * DH + r];
    __syncthreads();
    float logit = -1e30f;
    if (r < NR) {
        const float4* E = (const float4*)(rel_emb + (size_t)r * DH);
        const float4* q = (const float4*)scq;
        float acc = 0.f;
#pragma unroll 8
        for (int k = 0; k < DH / 4; k++) {
            float4 w = E[k]; float4 x = q[k];
            acc += w.x * x.x + w.y * x.y + w.z * x.z + w.w * x.w;
        }
        logit = acc;
    }
    red[r] = logit; redi[r] = (r < NR) ? r : 0x7fffffff;
    __syncthreads();
    for (int s = 256; s > 0; s >>= 1) {
        if (r < s) {
            float a = red[r], c = red[r + s];
            int ia = redi[r], ic = redi[r + s];
            if (c > a || (c == a && ic < ia)) { red[r] = c; redi[r] = ic; }
        }
        __syncthreads();
    }
    float mx = red[0];
    int amax = redi[0];
    __syncthreads();
    float e = (r < NR) ? expf(logit - mx) : 0.f;
    red[r] = e;
    __syncthreads();
    for (int s = 256; s > 0; s >>= 1) {
        if (r < s) red[r] += red[r + s];
        __syncthreads();
    }
    float sum = red[0];
    if (r < NR) {
        float p = e / sum;
        g_relT[r * B + b] = p;
        if (t == 0 && r == questions[b]) g_gt[b] = p;
    }
    if (r == 0) g_argmax[t * B + b] = amax;
}

// ---------------- per-batch mask flags ----------------
__global__ void k_flags(int t) {
    int b = threadIdx.x;
    int prev = g_argmax[(t - 1) * B + b], curr = g_argmax[t * B + b];
    int d = prev - curr; if (d < 0) d = -d;
    int mn = prev < curr ? prev : curr;
    g_cond[b] = (d == 1 && (mn & 1) == 0) ? 1.f : 0.f;
    if (t == T_STEPS - 1) {
        int ns = 0;
        for (int k = 0; k < T_STEPS; k++) ns += (g_argmax[k * B + b] == 0);
        g_m3[b] = (ns == 1) ? 1.f : 0.f;
    }
}

// ---------------- zero next-state buffer (+ g_nact once) ----------------
__global__ void k_zero_buf(int which) {
    int i = blockIdx.x * blockDim.x + threadIdx.x;
    if (i < NE * B) g_e[which][i] = 0.f;
    if (which == T_STEPS && i == 0) g_nact = 0;
}
__global__ void k_zero_sums() {
    g_sums[threadIdx.x] = 0.f;
}

// ---------------- follow: mask-gated scatter (thread per triple, ballot compaction) ----------------
__global__ void __launch_bounds__(256) k_follow(const int* __restrict__ subj,
                                                const int* __restrict__ rel,
                                                const int* __restrict__ obj, int t) {
    int i = blockIdx.x * 256 + threadIdx.x;     // triple id
    int lane = threadIdx.x & 31;
    int s = 0;
    bool act = false;
    if (i < NT) {
        s = __ldg(subj + i);
        act = (g_mask[s] != 0);
    }
    unsigned m = __ballot_sync(0xffffffffu, act);
    while (m) {
        int j = __ffs(m) - 1; m &= m - 1;
        int ti = __shfl_sync(0xffffffffu, i, j);
        int ts = __shfl_sync(0xffffffffu, s, j);
        int tr = __ldg(rel + ti);
        int to = __ldg(obj + ti);
        float x = g_e[t][(size_t)ts * B + lane] * g_relT[tr * B + lane];
        if (x != 0.f) atomicAdd(&g_e[t + 1][(size_t)to * B + lane], x);
    }
}

// ---------------- post-follow pointwise + mask build (+ active list at final step) ----------------
__global__ void k_post(int t) {
    int idx = blockIdx.x * blockDim.x + threadIdx.x;
    if (idx >= NE * B) return;
    int b = idx & 31;
    int ent = idx >> 5;                             // constant within warp
    float v = g_e[t + 1][idx];
    if (t == 0) v -= g_ansT[idx] * g_gt[b];
    if (v > 1.f) v = 1.f;                           // v/z with z=v where v>1
    if (t >= 1) {
        if (g_cond[b] != 0.f && g_e[t - 1][idx] > 0.9f) v = 0.f;
    }
    if (t == T_STEPS - 1) v *= (1.f - g_m3[b] * g_e[0][idx]);
    g_e[t + 1][idx] = v;
    unsigned m = __ballot_sync(0xffffffffu, v != 0.f);
    if (b == 0) {
        g_mask[ent] = (m != 0u) ? 1 : 0;
        if (t == T_STEPS - 1 && m != 0u) {
            int pos = atomicAdd(&g_nact, 1);
            g_act[pos] = ent;
        }
    }
}

// ---------------- per-batch sums of e_score ----------------
__global__ void k_sums() {
    __shared__ float part[8][32];
    int tid = threadIdx.x, lane = tid & 31, wp = tid >> 5;
    float acc = 0.f;
    for (int idx = blockIdx.x * 256 + tid; idx < NE * B; idx += gridDim.x * 256)
        acc += g_e[T_STEPS][idx];                   // b == lane by construction
    part[wp][lane] = acc;
    __syncthreads();
    if (wp == 0) {
        float s = 0.f;
        for (int k = 0; k < 8; k++) s += part[k][lane];
        atomicAdd(&g_sums[lane], s);
    }
}

// ---------------- e_score output: transpose (NE,B) -> (B,NE) ----------------
__global__ void k_outT(float* __restrict__ out) {
    __shared__ float tile[32][33];
    int i0 = blockIdx.x * 32;
    int tx = threadIdx.x, ty = threadIdx.y;
    tile[ty][tx] = g_e[T_STEPS][(size_t)(i0 + ty) * B + tx];
    __syncthreads();
    out[(size_t)ty * NE + i0 + tx] = tile[tx][ty];
}

// ---------------- h = (e_score / (sum+1e-6)) @ ent_emb over ACTIVE rows only ----------------
__global__ void __launch_bounds__(512) k_h(const float* __restrict__ ent_emb) {
    int b = threadIdx.x & 31;
    int dg = threadIdx.x >> 5;                      // 0..15, dims dg*32..dg*32+31
    float inv = 1.f / (g_sums[b] + 1e-6f);
    float acc[32];
#pragma unroll
    for (int k = 0; k < 32; k++) acc[k] = 0.f;
    int nact = g_nact;
    for (int a = blockIdx.x * 32; a < nact; a += gridDim.x * 32) {
        int aend = a + 32; if (aend > nact) aend = nact;
        for (int aa = a; aa < aend; aa++) {
            int i = g_act[aa];
            float ev = g_e[T_STEPS][(size_t)i * B + b] * inv;
            const float4* wp = (const float4*)(ent_emb + (size_t)i * DH + dg * 32);
#pragma unroll
            for (int k = 0; k < 8; k++) {
                float4 w = wp[k];
                acc[4 * k + 0] += ev * w.x; acc[4 * k + 1] += ev * w.y;
                acc[4 * k + 2] += ev * w.z; acc[4 * k + 3] += ev * w.w;
            }
        }
    }
    // partial slot: [blk][d*B + b], coalesced over b
    float* dst = g_hpart[blockIdx.x];
#pragma unroll
    for (int k = 0; k < 32; k++)
        dst[(dg * 32 + k) * B + b] = acc[k];
}

// ---------------- reduce partials -> g_h[b*DH+d] ----------------
__global__ void k_hred() {
    int tid = blockIdx.x * 256 + threadIdx.x;       // tid over DH*B, (d, b) with b fast
    if (tid >= DH * B) return;
    int b = tid & 31, d = tid >> 5;
    float s = 0.f;
    for (int blk = 0; blk < HB; blk++)
        s += g_hpart[blk][d * B + b];
    g_h[b * DH + d] = s;
}

// ---------------- pred = h @ ent_emb^T + bias  (register-tiled 4x4, 32x128 block tile) ----------------
__global__ void __launch_bounds__(256) k_pred(const float* __restrict__ ent_emb,
                                              const float* __restrict__ ent_bias,
                                              float* __restrict__ out) {
    __shared__ float sh[32][36];    // [kk][m], stride 36 floats (16B aligned)
    __shared__ float se[32][128];   // [kk][n]
    int i0 = blockIdx.x * 128;
    int tid = threadIdx.x;
    int tx = tid & 31;              // n0 = tx*4
    int ty = tid >> 5;              // m0 = ty*4
    float acc[4][4];
#pragma unroll
    for (int a = 0; a < 4; a++)
#pragma unroll
        for (int c = 0; c < 4; c++) acc[a][c] = 0.f;

    for (int kt = 0; kt < DH; kt += 32) {
        // load h tile: thread -> (m = tid>>3, kq = tid&7), one float4 along k
        {
            int m = tid >> 3, kq = tid & 7;
            float4 v = *(const float4*)(g_h + m * DH + kt + kq * 4);
            sh[kq * 4 + 0][m] = v.x; sh[kq * 4 + 1][m] = v.y;
            sh[kq * 4 + 2][m] = v.z; sh[kq * 4 + 3][m] = v.w;
        }
        // load ent_emb tile: 128 n-rows x 8 float4 chunks; 4 per thread
        {
            int n = tid & 127;
            int kq0 = tid >> 7;     // 0..1
            int i = i0 + n;
#pragma unroll
            for (int q = 0; q < 4; q++) {
                int kq = kq0 + q * 2;
                float4 v = (i < NE) ? *(const float4*)(ent_emb + (size_t)i * DH + kt + kq * 4)
                                    : make_float4(0.f, 0.f, 0.f, 0.f);
                se[kq * 4 + 0][n] = v.x; se[kq * 4 + 1][n] = v.y;
                se[kq * 4 + 2][n] = v.z; se[kq * 4 + 3][n] = v.w;
            }
        }
        __syncthreads();
#pragma unroll
        for (int kk = 0; kk < 32; kk++) {
            float4 av = *(const float4*)&sh[kk][ty * 4];
            float4 bv = *(const float4*)&se[kk][tx * 4];
            float am[4] = {av.x, av.y, av.z, av.w};
            float bn[4] = {bv.x, bv.y, bv.z, bv.w};
#pragma unroll
            for (int a = 0; a < 4; a++)
#pragma unroll
                for (int c = 0; c < 4; c++)
                    acc[a][c] += am[a] * bn[c];
        }
        __syncthreads();
    }
#pragma unroll
    for (int a = 0; a < 4; a++) {
        int m = ty * 4 + a;
        int nb = i0 + tx * 4;
#pragma unroll
        for (int c = 0; c < 4; c++) {
            int nn = nb + c;
            if (nn < NE) out[(size_t)m * NE + nn] = acc[a][c] + ent_bias[nn];
        }
    }
}

// ---------------- driver ----------------
extern "C" void kernel_launch(void* const* d_in, const int* in_sizes, int n_in,
                              void* d_out, int out_size) {
    const int*   questions = (const int*)d_in[0];
    const float* e_s       = (const float*)d_in[1];
    const float* answers   = (const float*)d_in[2];
    const int*   subj      = (const int*)d_in[3];
    const int*   rel       = (const int*)d_in[4];
    const int*   obj       = (const int*)d_in[5];
    const float* rel_emb   = (const float*)d_in[6];
    const float* step_W    = (const float*)d_in[7];
    const float* step_b    = (const float*)d_in[8];
    const float* ent_emb   = (const float*)d_in[9];
    const float* ent_bias  = (const float*)d_in[10];
    float* out = (float*)d_out;

    k_transpose_in<<<dim3(NE / 32, 2), dim3(32, 32)>>>(e_s, answers);

    for (int t = 0; t < T_STEPS; t++) {
        k_cq<<<B, DH>>>(questions, rel_emb, step_W, step_b, t);
        k_rel<<<B, 512>>>(rel_emb, questions, t);
        if (t > 0) k_flags<<<1, B>>>(t);
        k_zero_buf<<<(NE * B + 255) / 256, 256>>>(t + 1);
        k_follow<<<(NT + 255) / 256, 256>>>(subj, rel, obj, t);
        k_post<<<(NE * B + 255) / 256, 256>>>(t);
    }

    k_zero_sums<<<1, B>>>();
    k_sums<<<512, 256>>>();
    k_outT<<<NE / 32, dim3(32, 32)>>>(out);
    k_h<<<HB, 512>>>(ent_emb);
    k_hred<<<(DH * B + 255) / 256, 256>>>();
    k_pred<<<(NE + 127) / 128, 256>>>(ent_emb, ent_bias, out + (size_t)B * NE);
}

// round 3
// speedup vs baseline: 1.9730x; 1.1268x over previous
#include <cuda_runtime.h>
#include <math.h>

#define NE 100000
#define NR 400
#define NT 1000000
#define B  32
#define DH 512
#define T_STEPS 3
#define HB 148   // k_h partial blocks

// ---------------- device scratch ----------------
__device__ float g_e[T_STEPS + 1][NE * B];   // entity dists, (NE,B) layout
__device__ float g_relT[NR * B];
__device__ float g_cq[B * DH];
__device__ int   g_argmax[T_STEPS * B];
__device__ float g_gt[B];
__device__ float g_cond[B];
__device__ float g_m3[B];
__device__ float g_sums[B];
__device__ float g_h[B * DH];
__device__ unsigned char g_mask[NE];
__device__ int   g_nact;
__device__ int   g_act[NE];
__device__ int   g_ansIdx[B];
__device__ float g_ansVal[B];
__device__ float g_hpart[HB][DH * B];

// ---------------- f32x2 helpers ----------------
__device__ __forceinline__ unsigned long long pk2(float v) {
    unsigned long long r;
    asm("mov.b64 %0,{%1,%1};" : "=l"(r) : "f"(v));
    return r;
}
__device__ __forceinline__ void fma2(unsigned long long& d, unsigned long long a,
                                     unsigned long long b) {
    asm("fma.rn.f32x2 %0,%1,%2,%0;" : "+l"(d) : "l"(a), "l"(b));
}
__device__ __forceinline__ void upk2(unsigned long long v, float& lo, float& hi) {
    asm("mov.b64 {%0,%1},%2;" : "=f"(lo), "=f"(hi) : "l"(v));
}

// ---------------- transpose e_s (B,NE) -> (NE,B), + initial mask ----------------
__global__ void k_transpose_in(const float* __restrict__ es) {
    __shared__ float tile[32][33];
    int i0 = blockIdx.x * 32;
    int tx = threadIdx.x, ty = threadIdx.y;
    tile[ty][tx] = es[(size_t)ty * NE + i0 + tx];
    __syncthreads();
    float v = tile[tx][ty];
    g_e[0][(size_t)(i0 + ty) * B + tx] = v;
    unsigned m = __ballot_sync(0xffffffffu, v != 0.f);
    if (tx == 0) g_mask[i0 + ty] = (m != 0u) ? 1 : 0;
}

// ---------------- find one-hot answer index/value per batch ----------------
__global__ void k_findans(const float* __restrict__ ans) {
    int b = blockIdx.x;
    int e = blockIdx.y * 1024 + threadIdx.x * 4;
    if (e >= NE) return;
    float4 v = *(const float4*)&ans[(size_t)b * NE + e];
    if (v.x != 0.f) { g_ansIdx[b] = e;     g_ansVal[b] = v.x; }
    if (v.y != 0.f) { g_ansIdx[b] = e + 1; g_ansVal[b] = v.y; }
    if (v.z != 0.f) { g_ansIdx[b] = e + 2; g_ansVal[b] = v.z; }
    if (v.w != 0.f) { g_ansIdx[b] = e + 3; g_ansVal[b] = v.w; }
}

// ---------------- cq_t = tanh(q_emb @ W[t]^T + b[t]) ----------------
__global__ void k_cq(const int* __restrict__ questions,
                     const float* __restrict__ rel_emb,
                     const float* __restrict__ step_W,
                     const float* __restrict__ step_b, int t) {
    __shared__ float q[DH];
    int b = blockIdx.x, j = threadIdx.x;
    int qi = questions[b];
    q[j] = rel_emb[(size_t)qi * DH + j];
    __syncthreads();
    const float4* W = (const float4*)(step_W + (size_t)t * DH * DH + (size_t)j * DH);
    const float4* qv = (const float4*)q;
    float acc = step_b[t * DH + j];
#pragma unroll 8
    for (int k = 0; k < DH / 4; k++) {
        float4 w = W[k]; float4 x = qv[k];
        acc += w.x * x.x + w.y * x.y + w.z * x.z + w.w * x.w;
    }
    g_cq[b * DH + j] = tanhf(acc);
}

// ---------------- rel_dist = softmax(cq @ rel_emb^T), + argmax, + gt ----------------
__global__ void k_rel(const float* __restrict__ rel_emb,
                      const int* __restrict__ questions, int t) {
    __shared__ float scq[DH];
    __shared__ float red[512];
    __shared__ int   redi[512];
    int b = blockIdx.x, r = threadIdx.x;
    scq[r] = g_cq[b * DH + r];
    __syncthreads();
    float logit = -1e30f;
    if (r < NR) {
        const float4* E = (const float4*)(rel_emb + (size_t)r * DH);
        const float4* q = (const float4*)scq;
        float acc = 0.f;
#pragma unroll 8
        for (int k = 0; k < DH / 4; k++) {
            float4 w = E[k]; float4 x = q[k];
            acc += w.x * x.x + w.y * x.y + w.z * x.z + w.w * x.w;
        }
        logit = acc;
    }
    red[r] = logit; redi[r] = (r < NR) ? r : 0x7fffffff;
    __syncthreads();
    for (int s = 256; s > 0; s >>= 1) {
        if (r < s) {
            float a = red[r], c = red[r + s];
            int ia = redi[r], ic = redi[r + s];
            if (c > a || (c == a && ic < ia)) { red[r] = c; redi[r] = ic; }
        }
        __syncthreads();
    }
    float mx = red[0];
    int amax = redi[0];
    __syncthreads();
    float e = (r < NR) ? expf(logit - mx) : 0.f;
    red[r] = e;
    __syncthreads();
    for (int s = 256; s > 0; s >>= 1) {
        if (r < s) red[r] += red[r + s];
        __syncthreads();
    }
    float sum = red[0];
    if (r < NR) {
        float p = e / sum;
        g_relT[r * B + b] = p;
        if (t == 0 && r == questions[b]) g_gt[b] = p;
    }
    if (r == 0) g_argmax[t * B + b] = amax;
}

// ---------------- per-batch mask flags ----------------
__global__ void k_flags(int t) {
    int b = threadIdx.x;
    int prev = g_argmax[(t - 1) * B + b], curr = g_argmax[t * B + b];
    int d = prev - curr; if (d < 0) d = -d;
    int mn = prev < curr ? prev : curr;
    g_cond[b] = (d == 1 && (mn & 1) == 0) ? 1.f : 0.f;
    if (t == T_STEPS - 1) {
        int ns = 0;
        for (int k = 0; k < T_STEPS; k++) ns += (g_argmax[k * B + b] == 0);
        g_m3[b] = (ns == 1) ? 1.f : 0.f;
    }
}

// ---------------- vectorized zero of next-state buffer ----------------
__global__ void k_zero_buf(int which) {
    float4 z = make_float4(0.f, 0.f, 0.f, 0.f);
    int n4 = NE * B / 4;
    for (int i = blockIdx.x * blockDim.x + threadIdx.x; i < n4;
         i += gridDim.x * blockDim.x)
        ((float4*)g_e[which])[i] = z;
    if (which == T_STEPS && blockIdx.x == 0 && threadIdx.x < 8) {
        ((float4*)g_sums)[threadIdx.x] = z;
        if (threadIdx.x == 0) g_nact = 0;
    }
}

// ---------------- follow: mask-gated scatter ----------------
__global__ void __launch_bounds__(256) k_follow(const int* __restrict__ subj,
                                                const int* __restrict__ rel,
                                                const int* __restrict__ obj, int t) {
    int i = blockIdx.x * 256 + threadIdx.x;
    int lane = threadIdx.x & 31;
    int s = 0;
    bool act = false;
    if (i < NT) {
        s = __ldg(subj + i);
        act = (g_mask[s] != 0);
    }
    unsigned m = __ballot_sync(0xffffffffu, act);
    while (m) {
        int j = __ffs(m) - 1; m &= m - 1;
        int ti = __shfl_sync(0xffffffffu, i, j);
        int ts = __shfl_sync(0xffffffffu, s, j);
        int tr = __ldg(rel + ti);
        int to = __ldg(obj + ti);
        float x = g_e[t][(size_t)ts * B + lane] * g_relT[tr * B + lane];
        if (x != 0.f) atomicAdd(&g_e[t + 1][(size_t)to * B + lane], x);
    }
}

// ---------------- mid-step post (t = 0 or 1), float4 vectorized ----------------
__global__ void __launch_bounds__(256) k_post(int t) {
    int idx4 = blockIdx.x * 256 + threadIdx.x;   // over NE*B/4
    int lane = threadIdx.x & 31;
    int b4 = idx4 & 7;
    int ent = idx4 >> 3;
    int b0 = b4 * 4;
    float4 v = ((const float4*)g_e[t + 1])[idx4];
    float4 ov = v;
    if (t == 0) {
        float* vp = &v.x;
#pragma unroll
        for (int c = 0; c < 4; c++) {
            int b = b0 + c;
            if (ent == g_ansIdx[b]) vp[c] -= g_ansVal[b] * g_gt[b];
        }
    }
    v.x = fminf(v.x, 1.f); v.y = fminf(v.y, 1.f);
    v.z = fminf(v.z, 1.f); v.w = fminf(v.w, 1.f);
    if (t >= 1) {
        float c0 = g_cond[b0], c1 = g_cond[b0 + 1], c2 = g_cond[b0 + 2], c3 = g_cond[b0 + 3];
        if (c0 + c1 + c2 + c3 != 0.f) {
            float4 pv = ((const float4*)g_e[t - 1])[idx4];
            if (c0 != 0.f && pv.x > 0.9f) v.x = 0.f;
            if (c1 != 0.f && pv.y > 0.9f) v.y = 0.f;
            if (c2 != 0.f && pv.z > 0.9f) v.z = 0.f;
            if (c3 != 0.f && pv.w > 0.9f) v.w = 0.f;
        }
    }
    bool nz = (v.x != 0.f) | (v.y != 0.f) | (v.z != 0.f) | (v.w != 0.f);
    bool changed = (v.x != ov.x) | (v.y != ov.y) | (v.z != ov.z) | (v.w != ov.w);
    if (changed) ((float4*)g_e[t + 1])[idx4] = v;
    unsigned m = __ballot_sync(0xffffffffu, nz);
    if ((threadIdx.x & 7) == 0)
        g_mask[ent] = ((m >> (lane & ~7)) & 0xffu) ? 1 : 0;
}

// ---------------- final post: masks + e_score out (transposed) + sums + active list ----------------
__global__ void __launch_bounds__(256) k_post_last(float* __restrict__ out) {
    __shared__ float tile[32][33];
    int tid = threadIdx.x;
    int e_base = blockIdx.x * 32;
    int b4 = tid & 7, el = tid >> 3;
    int b0 = b4 * 4;
    int idx4 = blockIdx.x * 256 + tid;
    float4 v = ((const float4*)g_e[T_STEPS])[idx4];
    float4 ov = v;
    v.x = fminf(v.x, 1.f); v.y = fminf(v.y, 1.f);
    v.z = fminf(v.z, 1.f); v.w = fminf(v.w, 1.f);
    {
        float c0 = g_cond[b0], c1 = g_cond[b0 + 1], c2 = g_cond[b0 + 2], c3 = g_cond[b0 + 3];
        if (c0 + c1 + c2 + c3 != 0.f) {
            float4 pv = ((const float4*)g_e[T_STEPS - 1])[idx4];
            if (c0 != 0.f && pv.x > 0.9f) v.x = 0.f;
            if (c1 != 0.f && pv.y > 0.9f) v.y = 0.f;
            if (c2 != 0.f && pv.z > 0.9f) v.z = 0.f;
            if (c3 != 0.f && pv.w > 0.9f) v.w = 0.f;
        }
    }
    {
        float m0 = g_m3[b0], m1 = g_m3[b0 + 1], m2 = g_m3[b0 + 2], m3 = g_m3[b0 + 3];
        if (m0 + m1 + m2 + m3 != 0.f) {
            float4 e0 = ((const float4*)g_e[0])[idx4];
            v.x *= 1.f - m0 * e0.x; v.y *= 1.f - m1 * e0.y;
            v.z *= 1.f - m2 * e0.z; v.w *= 1.f - m3 * e0.w;
        }
    }
    bool nz = (v.x != 0.f) | (v.y != 0.f) | (v.z != 0.f) | (v.w != 0.f);
    bool changed = (v.x != ov.x) | (v.y != ov.y) | (v.z != ov.z) | (v.w != ov.w);
    if (changed) ((float4*)g_e[T_STEPS])[idx4] = v;
    tile[b0 + 0][el] = v.x; tile[b0 + 1][el] = v.y;
    tile[b0 + 2][el] = v.z; tile[b0 + 3][el] = v.w;
    int any = __syncthreads_or(nz ? 1 : 0);
    // e_score output, transposed writes (coalesced per warp)
    int lane = tid & 31, warp = tid >> 5;
#pragma unroll
    for (int r = 0; r < 4; r++) {
        int b = warp + r * 8;
        out[(size_t)b * NE + e_base + lane] = tile[b][lane];
    }
    if (any && tid < 32) {
        // per-batch sums
        float s = 0.f;
#pragma unroll
        for (int e = 0; e < 32; e++) s += tile[tid][e];
        if (s != 0.f) atomicAdd(&g_sums[tid], s);
        // active entity list (warp-aggregated append)
        float nzv = 0.f;
#pragma unroll
        for (int b = 0; b < 32; b++) nzv += fabsf(tile[b][tid]);
        bool act = (nzv != 0.f);
        unsigned mm = __ballot_sync(0xffffffffu, act);
        if (mm) {
            int leader = __ffs(mm) - 1;
            int base = 0;
            if (tid == leader) base = atomicAdd(&g_nact, __popc(mm));
            base = __shfl_sync(0xffffffffu, base, leader);
            if (act) g_act[base + __popc(mm & ((1u << tid) - 1u))] = e_base + tid;
        }
    }
}

// ---------------- h = (e_score / (sum+1e-6)) @ ent_emb over ACTIVE rows ----------------
__global__ void __launch_bounds__(512) k_h(const float* __restrict__ ent_emb) {
    int b = threadIdx.x & 31;
    int dg = threadIdx.x >> 5;
    float inv = 1.f / (g_sums[b] + 1e-6f);
    float acc[32];
#pragma unroll
    for (int k = 0; k < 32; k++) acc[k] = 0.f;
    int nact = g_nact;
    for (int a = blockIdx.x * 32; a < nact; a += gridDim.x * 32) {
        int aend = a + 32; if (aend > nact) aend = nact;
        for (int aa = a; aa < aend; aa++) {
            int i = g_act[aa];
            float ev = g_e[T_STEPS][(size_t)i * B + b] * inv;
            const float4* wp = (const float4*)(ent_emb + (size_t)i * DH + dg * 32);
#pragma unroll
            for (int k = 0; k < 8; k++) {
                float4 w = wp[k];
                acc[4 * k + 0] += ev * w.x; acc[4 * k + 1] += ev * w.y;
                acc[4 * k + 2] += ev * w.z; acc[4 * k + 3] += ev * w.w;
            }
        }
    }
    float* dst = g_hpart[blockIdx.x];
#pragma unroll
    for (int k = 0; k < 32; k++)
        dst[(dg * 32 + k) * B + b] = acc[k];
}

__global__ void k_hred() {
    int tid = blockIdx.x * 256 + threadIdx.x;
    if (tid >= DH * B) return;
    int b = tid & 31, d = tid >> 5;
    float s = 0.f;
    for (int blk = 0; blk < HB; blk++)
        s += g_hpart[blk][d * B + b];
    g_h[b * DH + d] = s;
}

// ---------------- pred = h @ ent_emb^T + bias  (f32x2 FFMA2, 32x256 tile) ----------------
__global__ void __launch_bounds__(256) k_pred(const float* __restrict__ ent_emb,
                                              const float* __restrict__ ent_bias,
                                              float* __restrict__ out) {
    __shared__ float sh[32][36];     // [k][m]
    __shared__ float se[32][256];    // [k][n], XOR-swizzled columns: col = n ^ (4*(k>>2))
    int i0 = blockIdx.x * 256;
    int tid = threadIdx.x;
    int nt = tid & 31, mt = tid >> 5;
    int n0 = nt * 8, m0 = mt * 4;
    unsigned long long acc[4][4];
#pragma unroll
    for (int a = 0; a < 4; a++)
#pragma unroll
        for (int c = 0; c < 4; c++) acc[a][c] = 0ull;

    int kq = tid & 7;          // k-quad for loads
    int rbase = tid >> 3;      // 0..31

    for (int kt = 0; kt < DH; kt += 32) {
        // h tile: [32 m][32 k]
        {
            int m = tid >> 3, kqh = tid & 7;
            float4 hv = *(const float4*)(g_h + m * DH + kt + kqh * 4);
            sh[kqh * 4 + 0][m] = hv.x; sh[kqh * 4 + 1][m] = hv.y;
            sh[kqh * 4 + 2][m] = hv.z; sh[kqh * 4 + 3][m] = hv.w;
        }
        // ent_emb tile: coalesced loads, swizzled scatter stores
#pragma unroll
        for (int r = 0; r < 8; r++) {
            int row = rbase + r * 32;
            int i = i0 + row;
            float4 v = (i < NE) ? *(const float4*)(ent_emb + (size_t)i * DH + kt + kq * 4)
                                : make_float4(0.f, 0.f, 0.f, 0.f);
            int col = row ^ (kq * 4);      // swizzle: 4*(k>>2) with k = kq*4+j
            se[kq * 4 + 0][col] = v.x; se[kq * 4 + 1][col] = v.y;
            se[kq * 4 + 2][col] = v.z; se[kq * 4 + 3][col] = v.w;
        }
        __syncthreads();
#pragma unroll
        for (int kk = 0; kk < 32; kk++) {
            float4 av = *(const float4*)&sh[kk][m0];
            int q2 = (kk >> 2) * 4;
            int off = n0 ^ (q2 & 24);
            int l4 = q2 & 4;
            ulonglong2 P = *(const ulonglong2*)&se[kk][off + l4];        // cols n0..n0+3
            ulonglong2 Q = *(const ulonglong2*)&se[kk][off + (4 ^ l4)];  // cols n0+4..n0+7
            unsigned long long am0 = pk2(av.x), am1 = pk2(av.y);
            unsigned long long am2 = pk2(av.z), am3 = pk2(av.w);
            fma2(acc[0][0], am0, P.x); fma2(acc[0][1], am0, P.y);
            fma2(acc[0][2], am0, Q.x); fma2(acc[0][3], am0, Q.y);
            fma2(acc[1][0], am1, P.x); fma2(acc[1][1], am1, P.y);
            fma2(acc[1][2], am1, Q.x); fma2(acc[1][3], am1, Q.y);
            fma2(acc[2][0], am2, P.x); fma2(acc[2][1], am2, P.y);
            fma2(acc[2][2], am2, Q.x); fma2(acc[2][3], am2, Q.y);
            fma2(acc[3][0], am3, P.x); fma2(acc[3][1], am3, P.y);
            fma2(acc[3][2], am3, Q.x); fma2(acc[3][3], am3, Q.y);
        }
        __syncthreads();
    }
    // epilogue
    int ng = i0 + n0;
    bool fast = (ng + 7 < NE);
    float bias[8];
    if (fast) {
        float4 b0 = *(const float4*)&ent_bias[ng];
        float4 b1 = *(const float4*)&ent_bias[ng + 4];
        bias[0] = b0.x; bias[1] = b0.y; bias[2] = b0.z; bias[3] = b0.w;
        bias[4] = b1.x; bias[5] = b1.y; bias[6] = b1.z; bias[7] = b1.w;
    } else {
#pragma unroll
        for (int c = 0; c < 8; c++) bias[c] = (ng + c < NE) ? ent_bias[ng + c] : 0.f;
    }
#pragma unroll
    for (int a = 0; a < 4; a++) {
        int m = m0 + a;
        float o[8];
#pragma unroll
        for (int c = 0; c < 4; c++) upk2(acc[a][c], o[2 * c], o[2 * c + 1]);
#pragma unroll
        for (int c = 0; c < 8; c++) o[c] += bias[c];
        if (fast) {
            *(float4*)&out[(size_t)m * NE + ng] = make_float4(o[0], o[1], o[2], o[3]);
            *(float4*)&out[(size_t)m * NE + ng + 4] = make_float4(o[4], o[5], o[6], o[7]);
        } else {
#pragma unroll
            for (int c = 0; c < 8; c++)
                if (ng + c < NE) out[(size_t)m * NE + ng + c] = o[c];
        }
    }
}

// ---------------- driver ----------------
extern "C" void kernel_launch(void* const* d_in, const int* in_sizes, int n_in,
                              void* d_out, int out_size) {
    const int*   questions = (const int*)d_in[0];
    const float* e_s       = (const float*)d_in[1];
    const float* answers   = (const float*)d_in[2];
    const int*   subj      = (const int*)d_in[3];
    const int*   rel       = (const int*)d_in[4];
    const int*   obj       = (const int*)d_in[5];
    const float* rel_emb   = (const float*)d_in[6];
    const float* step_W    = (const float*)d_in[7];
    const float* step_b    = (const float*)d_in[8];
    const float* ent_emb   = (const float*)d_in[9];
    const float* ent_bias  = (const float*)d_in[10];
    float* out = (float*)d_out;

    k_transpose_in<<<NE / 32, dim3(32, 32)>>>(e_s);
    k_findans<<<dim3(B, (NE + 1023) / 1024), 256>>>(answers);

    for (int t = 0; t < T_STEPS; t++) {
        k_cq<<<B, DH>>>(questions, rel_emb, step_W, step_b, t);
        k_rel<<<B, 512>>>(rel_emb, questions, t);
        if (t > 0) k_flags<<<1, B>>>(t);
        k_zero_buf<<<800, 256>>>(t + 1);
        k_follow<<<(NT + 255) / 256, 256>>>(subj, rel, obj, t);
        if (t < T_STEPS - 1)
            k_post<<<NE * B / 4 / 256, 256>>>(t);
        else
            k_post_last<<<NE / 32, 256>>>(out);
    }

    k_h<<<HB, 512>>>(ent_emb);
    k_hred<<<(DH * B + 255) / 256, 256>>>();
    k_pred<<<(NE + 255) / 256, 256>>>(ent_emb, ent_bias, out + (size_t)B * NE);
}

// round 5
// speedup vs baseline: 3.2541x; 1.6493x over previous
#include <cuda_runtime.h>
#include <math.h>

#define NE 100000
#define NR 400
#define NT 1000000
#define B  32
#define DH 512
#define T_STEPS 3
#define HB 148

// ---------------- device scratch (16B-aligned: vector-cast safety) ----------------
__device__ __align__(16) float g_e[T_STEPS + 1][NE * B];
__device__ __align__(16) float g_relT[T_STEPS][NR * B];
__device__ __align__(16) float g_cqA[T_STEPS][B][DH];
__device__ __align__(16) float g_logits[T_STEPS][B][NR];
__device__ int   g_argmax[T_STEPS * B];
__device__ float g_gt[B];
__device__ float g_cond[T_STEPS][B];
__device__ float g_m3[B];
__device__ __align__(16) float g_sums[B];
__device__ __align__(16) float g_h[B * DH];
__device__ unsigned char g_mask[NE];
__device__ int   g_nact;
__device__ int   g_act[NE];
__device__ int   g_ansIdx[B];
__device__ float g_ansVal[B];
__device__ __align__(16) float g_hpart[HB][DH * B];

// ---------------- f32x2 helpers ----------------
__device__ __forceinline__ unsigned long long pk2(float v) {
    unsigned long long r;
    asm("mov.b64 %0,{%1,%1};" : "=l"(r) : "f"(v));
    return r;
}
__device__ __forceinline__ void fma2(unsigned long long& d, unsigned long long a,
                                     unsigned long long b) {
    asm("fma.rn.f32x2 %0,%1,%2,%0;" : "+l"(d) : "l"(a), "l"(b));
}
__device__ __forceinline__ void upk2(unsigned long long v, float& lo, float& hi) {
    asm("mov.b64 {%0,%1},%2;" : "=f"(lo), "=f"(hi) : "l"(v));
}

__device__ __forceinline__ float dot4(float4 a, float4 b) {
    return a.x * b.x + a.y * b.y + a.z * b.z + a.w * b.w;
}

// ---------------- transpose e_s (B,NE) -> (NE,B), + initial mask ----------------
__global__ void k_transpose_in(const float* __restrict__ es) {
    __shared__ float tile[32][33];
    int i0 = blockIdx.x * 32;
    int tx = threadIdx.x, ty = threadIdx.y;
    tile[ty][tx] = es[(size_t)ty * NE + i0 + tx];
    __syncthreads();
    float v = tile[tx][ty];
    g_e[0][(size_t)(i0 + ty) * B + tx] = v;
    unsigned m = __ballot_sync(0xffffffffu, v != 0.f);
    if (tx == 0) g_mask[i0 + ty] = (m != 0u) ? 1 : 0;
}

// ---------------- find one-hot answer index/value per batch ----------------
__global__ void k_findans(const float* __restrict__ ans) {
    int b = blockIdx.x;
    int e = blockIdx.y * 1024 + threadIdx.x * 4;
    if (e >= NE) return;
    float4 v = *(const float4*)&ans[(size_t)b * NE + e];
    if (v.x != 0.f) { g_ansIdx[b] = e;     g_ansVal[b] = v.x; }
    if (v.y != 0.f) { g_ansIdx[b] = e + 1; g_ansVal[b] = v.y; }
    if (v.z != 0.f) { g_ansIdx[b] = e + 2; g_ansVal[b] = v.z; }
    if (v.w != 0.f) { g_ansIdx[b] = e + 3; g_ansVal[b] = v.w; }
}

// ---------------- all-steps cq: warp per output (t,b,j) ----------------
__global__ void __launch_bounds__(256) k_cq_all(const int* __restrict__ questions,
                                                const float* __restrict__ rel_emb,
                                                const float* __restrict__ step_W,
                                                const float* __restrict__ step_b) {
    int w = blockIdx.x * 8 + (threadIdx.x >> 5);   // global warp id
    int lane = threadIdx.x & 31;
    int j = w & (DH - 1);
    int b = (w >> 9) & (B - 1);
    int t = w >> 14;
    if (t >= T_STEPS) return;
    int qi = __ldg(questions + b);
    const float4* q = (const float4*)(rel_emb + (size_t)qi * DH);
    const float4* W = (const float4*)(step_W + (size_t)t * DH * DH + (size_t)j * DH);
    float acc = 0.f;
#pragma unroll
    for (int c = 0; c < 4; c++) {
        float4 qv = __ldg(q + lane + c * 32);
        float4 wv = __ldg(W + lane + c * 32);
        acc += dot4(qv, wv);
    }
#pragma unroll
    for (int s = 16; s > 0; s >>= 1) acc += __shfl_xor_sync(0xffffffffu, acc, s);
    if (lane == 0)
        g_cqA[t][b][j] = tanhf(acc + __ldg(step_b + t * DH + j));
}

// ---------------- all-steps rel logits: warp per output (t,b,r) ----------------
__global__ void __launch_bounds__(256) k_logits_all(const float* __restrict__ rel_emb) {
    int w = blockIdx.x * 8 + (threadIdx.x >> 5);
    int lane = threadIdx.x & 31;
    int r = w % NR;
    int tb = w / NR;
    int b = tb & (B - 1);
    int t = tb >> 5;
    if (t >= T_STEPS) return;
    const float4* q = (const float4*)&g_cqA[t][b][0];
    const float4* E = (const float4*)(rel_emb + (size_t)r * DH);
    float acc = 0.f;
#pragma unroll
    for (int c = 0; c < 4; c++) {
        float4 qv = q[lane + c * 32];
        float4 ev = __ldg(E + lane + c * 32);
        acc += dot4(qv, ev);
    }
#pragma unroll
    for (int s = 16; s > 0; s >>= 1) acc += __shfl_xor_sync(0xffffffffu, acc, s);
    if (lane == 0) g_logits[t][b][r] = acc;
}

// ---------------- softmax + argmax + gt over all (t,b) ----------------
__global__ void __launch_bounds__(512) k_softmax_all(const int* __restrict__ questions) {
    __shared__ float red[512];
    __shared__ int   redi[512];
    int t = blockIdx.x >> 5;
    int b = blockIdx.x & 31;
    int r = threadIdx.x;
    float logit = (r < NR) ? g_logits[t][b][r] : -1e30f;
    red[r] = logit; redi[r] = (r < NR) ? r : 0x7fffffff;
    __syncthreads();
    for (int s = 256; s > 0; s >>= 1) {
        if (r < s) {
            float a = red[r], c = red[r + s];
            int ia = redi[r], ic = redi[r + s];
            if (c > a || (c == a && ic < ia)) { red[r] = c; redi[r] = ic; }
        }
        __syncthreads();
    }
    float mx = red[0];
    int amax = redi[0];
    __syncthreads();
    float e = (r < NR) ? expf(logit - mx) : 0.f;
    red[r] = e;
    __syncthreads();
    for (int s = 256; s > 0; s >>= 1) {
        if (r < s) red[r] += red[r + s];
        __syncthreads();
    }
    float sum = red[0];
    if (r < NR) {
        float p = e / sum;
        g_relT[t][r * B + b] = p;
        if (t == 0 && r == questions[b]) g_gt[b] = p;
    }
    if (r == 0) g_argmax[t * B + b] = amax;
}

// ---------------- all flags ----------------
__global__ void k_flags_all() {
    int b = threadIdx.x;
    for (int t = 1; t < T_STEPS; t++) {
        int prev = g_argmax[(t - 1) * B + b], curr = g_argmax[t * B + b];
        int d = prev - curr; if (d < 0) d = -d;
        int mn = prev < curr ? prev : curr;
        g_cond[t][b] = (d == 1 && (mn & 1) == 0) ? 1.f : 0.f;
    }
    int ns = 0;
    for (int k = 0; k < T_STEPS; k++) ns += (g_argmax[k * B + b] == 0);
    g_m3[b] = (ns == 1) ? 1.f : 0.f;
}

// ---------------- zero all state buffers (t=1..3) + sums + nact ----------------
__global__ void k_zero_all() {
    float4 z = make_float4(0.f, 0.f, 0.f, 0.f);
    int n4 = T_STEPS * NE * B / 4;
    float4* base = (float4*)g_e[1];
    for (int i = blockIdx.x * blockDim.x + threadIdx.x; i < n4;
         i += gridDim.x * blockDim.x)
        base[i] = z;
    if (blockIdx.x == 0 && threadIdx.x < 8) {
        ((float4*)g_sums)[threadIdx.x] = z;
        if (threadIdx.x == 0) g_nact = 0;
    }
}

// ---------------- follow: mask-gated scatter ----------------
__global__ void __launch_bounds__(256) k_follow(const int* __restrict__ subj,
                                                const int* __restrict__ rel,
                                                const int* __restrict__ obj, int t) {
    int i = blockIdx.x * 256 + threadIdx.x;
    int lane = threadIdx.x & 31;
    int s = 0;
    bool act = false;
    if (i < NT) {
        s = __ldg(subj + i);
        act = (g_mask[s] != 0);
    }
    unsigned m = __ballot_sync(0xffffffffu, act);
    const float* relT = g_relT[t];
    while (m) {
        int j = __ffs(m) - 1; m &= m - 1;
        int ti = __shfl_sync(0xffffffffu, i, j);
        int ts = __shfl_sync(0xffffffffu, s, j);
        int tr = __ldg(rel + ti);
        int to = __ldg(obj + ti);
        float x = g_e[t][(size_t)ts * B + lane] * relT[tr * B + lane];
        if (x != 0.f) atomicAdd(&g_e[t + 1][(size_t)to * B + lane], x);
    }
}

// ---------------- mid-step post (t = 0 or 1) ----------------
__global__ void __launch_bounds__(256) k_post(int t) {
    int idx4 = blockIdx.x * 256 + threadIdx.x;
    int lane = threadIdx.x & 31;
    int b4 = idx4 & 7;
    int ent = idx4 >> 3;
    int b0 = b4 * 4;
    float4 v = ((const float4*)g_e[t + 1])[idx4];
    float4 ov = v;
    if (t == 0) {
        float* vp = &v.x;
#pragma unroll
        for (int c = 0; c < 4; c++) {
            int b = b0 + c;
            if (ent == g_ansIdx[b]) vp[c] -= g_ansVal[b] * g_gt[b];
        }
    }
    v.x = fminf(v.x, 1.f); v.y = fminf(v.y, 1.f);
    v.z = fminf(v.z, 1.f); v.w = fminf(v.w, 1.f);
    if (t >= 1) {
        float c0 = g_cond[t][b0], c1 = g_cond[t][b0 + 1];
        float c2 = g_cond[t][b0 + 2], c3 = g_cond[t][b0 + 3];
        if (c0 + c1 + c2 + c3 != 0.f) {
            float4 pv = ((const float4*)g_e[t - 1])[idx4];
            if (c0 != 0.f && pv.x > 0.9f) v.x = 0.f;
            if (c1 != 0.f && pv.y > 0.9f) v.y = 0.f;
            if (c2 != 0.f && pv.z > 0.9f) v.z = 0.f;
            if (c3 != 0.f && pv.w > 0.9f) v.w = 0.f;
        }
    }
    bool nz = (v.x != 0.f) | (v.y != 0.f) | (v.z != 0.f) | (v.w != 0.f);
    bool changed = (v.x != ov.x) | (v.y != ov.y) | (v.z != ov.z) | (v.w != ov.w);
    if (changed) ((float4*)g_e[t + 1])[idx4] = v;
    unsigned m = __ballot_sync(0xffffffffu, nz);
    if ((threadIdx.x & 7) == 0)
        g_mask[ent] = ((m >> (lane & ~7)) & 0xffu) ? 1 : 0;
}

// ---------------- final post: masks + e_score out + sums + active list ----------------
__global__ void __launch_bounds__(256) k_post_last(float* __restrict__ out) {
    __shared__ float tile[32][33];
    int tid = threadIdx.x;
    int e_base = blockIdx.x * 32;
    int b4 = tid & 7, el = tid >> 3;
    int b0 = b4 * 4;
    int idx4 = blockIdx.x * 256 + tid;
    const int TL = T_STEPS - 1;
    float4 v = ((const float4*)g_e[T_STEPS])[idx4];
    float4 ov = v;
    v.x = fminf(v.x, 1.f); v.y = fminf(v.y, 1.f);
    v.z = fminf(v.z, 1.f); v.w = fminf(v.w, 1.f);
    {
        float c0 = g_cond[TL][b0], c1 = g_cond[TL][b0 + 1];
        float c2 = g_cond[TL][b0 + 2], c3 = g_cond[TL][b0 + 3];
        if (c0 + c1 + c2 + c3 != 0.f) {
            float4 pv = ((const float4*)g_e[T_STEPS - 1])[idx4];
            if (c0 != 0.f && pv.x > 0.9f) v.x = 0.f;
            if (c1 != 0.f && pv.y > 0.9f) v.y = 0.f;
            if (c2 != 0.f && pv.z > 0.9f) v.z = 0.f;
            if (c3 != 0.f && pv.w > 0.9f) v.w = 0.f;
        }
    }
    {
        float m0 = g_m3[b0], m1 = g_m3[b0 + 1], m2 = g_m3[b0 + 2], m3 = g_m3[b0 + 3];
        if (m0 + m1 + m2 + m3 != 0.f) {
            float4 e0 = ((const float4*)g_e[0])[idx4];
            v.x *= 1.f - m0 * e0.x; v.y *= 1.f - m1 * e0.y;
            v.z *= 1.f - m2 * e0.z; v.w *= 1.f - m3 * e0.w;
        }
    }
    bool nz = (v.x != 0.f) | (v.y != 0.f) | (v.z != 0.f) | (v.w != 0.f);
    bool changed = (v.x != ov.x) | (v.y != ov.y) | (v.z != ov.z) | (v.w != ov.w);
    if (changed) ((float4*)g_e[T_STEPS])[idx4] = v;
    tile[b0 + 0][el] = v.x; tile[b0 + 1][el] = v.y;
    tile[b0 + 2][el] = v.z; tile[b0 + 3][el] = v.w;
    int any = __syncthreads_or(nz ? 1 : 0);
    int lane = tid & 31, warp = tid >> 5;
#pragma unroll
    for (int r = 0; r < 4; r++) {
        int b = warp + r * 8;
        out[(size_t)b * NE + e_base + lane] = tile[b][lane];
    }
    if (any && tid < 32) {
        float s = 0.f;
#pragma unroll
        for (int e = 0; e < 32; e++) s += tile[tid][e];
        if (s != 0.f) atomicAdd(&g_sums[tid], s);
        float nzv = 0.f;
#pragma unroll
        for (int b = 0; b < 32; b++) nzv += fabsf(tile[b][tid]);
        bool act = (nzv != 0.f);
        unsigned mm = __ballot_sync(0xffffffffu, act);
        if (mm) {
            int leader = __ffs(mm) - 1;
            int base = 0;
            if (tid == leader) base = atomicAdd(&g_nact, __popc(mm));
            base = __shfl_sync(0xffffffffu, base, leader);
            if (act) g_act[base + __popc(mm & ((1u << tid) - 1u))] = e_base + tid;
        }
    }
}

// ---------------- h over ACTIVE rows ----------------
__global__ void __launch_bounds__(512) k_h(const float* __restrict__ ent_emb) {
    int b = threadIdx.x & 31;
    int dg = threadIdx.x >> 5;
    float inv = 1.f / (g_sums[b] + 1e-6f);
    float acc[32];
#pragma unroll
    for (int k = 0; k < 32; k++) acc[k] = 0.f;
    int nact = g_nact;
    for (int a = blockIdx.x * 32; a < nact; a += gridDim.x * 32) {
        int aend = a + 32; if (aend > nact) aend = nact;
        for (int aa = a; aa < aend; aa++) {
            int i = g_act[aa];
            float ev = g_e[T_STEPS][(size_t)i * B + b] * inv;
            const float4* wp = (const float4*)(ent_emb + (size_t)i * DH + dg * 32);
#pragma unroll
            for (int k = 0; k < 8; k++) {
                float4 w = wp[k];
                acc[4 * k + 0] += ev * w.x; acc[4 * k + 1] += ev * w.y;
                acc[4 * k + 2] += ev * w.z; acc[4 * k + 3] += ev * w.w;
            }
        }
    }
    float* dst = g_hpart[blockIdx.x];
#pragma unroll
    for (int k = 0; k < 32; k++)
        dst[(dg * 32 + k) * B + b] = acc[k];
}

__global__ void k_hred() {
    int tid = blockIdx.x * 256 + threadIdx.x;
    if (tid >= DH * B) return;
    int b = tid & 31, d = tid >> 5;
    float s = 0.f;
    for (int blk = 0; blk < HB; blk++)
        s += g_hpart[blk][d * B + b];
    g_h[b * DH + d] = s;
}

// ---------------- pred = h @ ent_emb^T + bias (f32x2, 8m x 8n thread tile, 128 thr) ----------------
__global__ void __launch_bounds__(128) k_pred(const float* __restrict__ ent_emb,
                                              const float* __restrict__ ent_bias,
                                              float* __restrict__ out) {
    __shared__ float sh[32][36];     // [k][m]
    __shared__ float se[32][256];    // [k][n], col = n ^ (4*(k>>2))
    int i0 = blockIdx.x * 256;
    int tid = threadIdx.x;
    int nt = tid & 31, mt = tid >> 5;       // mt 0..3
    int n0 = nt * 8, m0 = mt * 8;
    unsigned long long acc[8][4];
#pragma unroll
    for (int a = 0; a < 8; a++)
#pragma unroll
        for (int c = 0; c < 4; c++) acc[a][c] = 0ull;

    int kq = tid & 7;
    int rbase = tid >> 3;                   // 0..15

    for (int kt = 0; kt < DH; kt += 32) {
        // h tile [32k][32m]: 256 float4 tasks / 128 threads = 2 each
#pragma unroll
        for (int p = 0; p < 2; p++) {
            int u = tid + p * 128;
            int m = u >> 3, kqh = u & 7;
            float4 hv = *(const float4*)(g_h + m * DH + kt + kqh * 4);
            sh[kqh * 4 + 0][m] = hv.x; sh[kqh * 4 + 1][m] = hv.y;
            sh[kqh * 4 + 2][m] = hv.z; sh[kqh * 4 + 3][m] = hv.w;
        }
        // ent_emb tile: 256 rows x 8 kquads = 2048 tasks / 128 threads = 16 rows each
#pragma unroll
        for (int r = 0; r < 16; r++) {
            int row = rbase + r * 16;
            int i = i0 + row;
            float4 v = (i < NE) ? *(const float4*)(ent_emb + (size_t)i * DH + kt + kq * 4)
                                : make_float4(0.f, 0.f, 0.f, 0.f);
            int col = row ^ (kq * 4);
            se[kq * 4 + 0][col] = v.x; se[kq * 4 + 1][col] = v.y;
            se[kq * 4 + 2][col] = v.z; se[kq * 4 + 3][col] = v.w;
        }
        __syncthreads();
#pragma unroll
        for (int kk = 0; kk < 32; kk++) {
            float4 av0 = *(const float4*)&sh[kk][m0];       // broadcast across warp
            float4 av1 = *(const float4*)&sh[kk][m0 + 4];
            int q2 = (kk >> 2) * 4;
            int off = n0 ^ (q2 & 24);
            int l4 = q2 & 4;
            ulonglong2 P = *(const ulonglong2*)&se[kk][off + l4];
            ulonglong2 Q = *(const ulonglong2*)&se[kk][off + (4 ^ l4)];
            unsigned long long am[8];
            am[0] = pk2(av0.x); am[1] = pk2(av0.y); am[2] = pk2(av0.z); am[3] = pk2(av0.w);
            am[4] = pk2(av1.x); am[5] = pk2(av1.y); am[6] = pk2(av1.z); am[7] = pk2(av1.w);
#pragma unroll
            for (int a = 0; a < 8; a++) {
                fma2(acc[a][0], am[a], P.x); fma2(acc[a][1], am[a], P.y);
                fma2(acc[a][2], am[a], Q.x); fma2(acc[a][3], am[a], Q.y);
            }
        }
        __syncthreads();
    }
    int ng = i0 + n0;
    bool fast = (ng + 7 < NE);
    float bias[8];
    if (fast) {
        float4 b0 = *(const float4*)&ent_bias[ng];
        float4 b1 = *(const float4*)&ent_bias[ng + 4];
        bias[0] = b0.x; bias[1] = b0.y; bias[2] = b0.z; bias[3] = b0.w;
        bias[4] = b1.x; bias[5] = b1.y; bias[6] = b1.z; bias[7] = b1.w;
    } else {
#pragma unroll
        for (int c = 0; c < 8; c++) bias[c] = (ng + c < NE) ? ent_bias[ng + c] : 0.f;
    }
#pragma unroll
    for (int a = 0; a < 8; a++) {
        int m = m0 + a;
        float o[8];
#pragma unroll
        for (int c = 0; c < 4; c++) upk2(acc[a][c], o[2 * c], o[2 * c + 1]);
#pragma unroll
        for (int c = 0; c < 8; c++) o[c] += bias[c];
        if (fast) {
            *(float4*)&out[(size_t)m * NE + ng] = make_float4(o[0], o[1], o[2], o[3]);
            *(float4*)&out[(size_t)m * NE + ng + 4] = make_float4(o[4], o[5], o[6], o[7]);
        } else {
#pragma unroll
            for (int c = 0; c < 8; c++)
                if (ng + c < NE) out[(size_t)m * NE + ng + c] = o[c];
        }
    }
}

// ---------------- driver ----------------
extern "C" void kernel_launch(void* const* d_in, const int* in_sizes, int n_in,
                              void* d_out, int out_size) {
    const int*   questions = (const int*)d_in[0];
    const float* e_s       = (const float*)d_in[1];
    const float* answers   = (const float*)d_in[2];
    const int*   subj      = (const int*)d_in[3];
    const int*   rel       = (const int*)d_in[4];
    const int*   obj       = (const int*)d_in[5];
    const float* rel_emb   = (const float*)d_in[6];
    const float* step_W    = (const float*)d_in[7];
    const float* step_b    = (const float*)d_in[8];
    const float* ent_emb   = (const float*)d_in[9];
    const float* ent_bias  = (const float*)d_in[10];
    float* out = (float*)d_out;

    k_transpose_in<<<NE / 32, dim3(32, 32)>>>(e_s);
    k_findans<<<dim3(B, (NE + 1023) / 1024), 256>>>(answers);
    k_zero_all<<<1200, 256>>>();

    // all-step MLP pipeline (no recurrence dependency)
    k_cq_all<<<T_STEPS * B * DH / 8, 256>>>(questions, rel_emb, step_W, step_b);
    k_logits_all<<<(T_STEPS * B * NR + 7) / 8, 256>>>(rel_emb);
    k_softmax_all<<<T_STEPS * B, 512>>>(questions);
    k_flags_all<<<1, B>>>();

    for (int t = 0; t < T_STEPS; t++) {
        k_follow<<<(NT + 255) / 256, 256>>>(subj, rel, obj, t);
        if (t < T_STEPS - 1)
            k_post<<<NE * B / 4 / 256, 256>>>(t);
        else
            k_post_last<<<NE / 32, 256>>>(out);
    }

    k_h<<<HB, 512>>>(ent_emb);
    k_hred<<<(DH * B + 255) / 256, 256>>>();
    // k_pred is a 128-thread design (__launch_bounds__(128)) — R4 failed by launching 256.
    k_pred<<<(NE + 255) / 256, 128>>>(ent_emb, ent_bias, out + (size_t)B * NE);
}